// round 2
// baseline (speedup 1.0000x reference)
#include <cuda_runtime.h>

// Problem constants
// x: [B=16, C=256, H=32, W=32]  -> viewed as [BC=4096, HW=1024]
// x1[b, p, cij] = x[b, cij, p];  30 layers of per-channel(p) BN+relu6 ODE steps.
// Each channel p (1024 of them) is fully independent: one CTA per channel.

constexpr int BVAL = 16;
constexpr int CVAL = 256;
constexpr int HW   = 1024;
constexpr int BC   = BVAL * CVAL;   // 4096
constexpr int NLAYERS = 30;

// Scratch: transposed input xt[p][bc] and transposed output yt[p][bc]
__device__ float g_xt[(size_t)HW * BC];
__device__ float g_yt[(size_t)HW * BC];

// ---------------------------------------------------------------------------
// Tiled transpose: out[c][r] = in[r][c], in is ROWS x COLS. Dims divide by 32.
// ---------------------------------------------------------------------------
template<int ROWS, int COLS>
__global__ __launch_bounds__(256) void tr_kernel(const float* __restrict__ in,
                                                 float* __restrict__ out) {
    __shared__ float tile[32][33];
    const int bx = blockIdx.x * 32;   // column base (in)
    const int by = blockIdx.y * 32;   // row base (in)
    const int tx = threadIdx.x, ty = threadIdx.y;
#pragma unroll
    for (int j = 0; j < 32; j += 8)
        tile[ty + j][tx] = in[(size_t)(by + ty + j) * COLS + (bx + tx)];
    __syncthreads();
#pragma unroll
    for (int j = 0; j < 32; j += 8)
        out[(size_t)(bx + ty + j) * ROWS + (by + tx)] = tile[tx][ty + j];
}

// ---------------------------------------------------------------------------
// Fused 30-layer ODE kernel. One CTA per channel p. 256 threads.
// Thread t owns elements (b=u, cij=t) for u = 0..15 -> 16 regs each of
// x1, y0, z. Per layer: block-reduce mean/var over the 4096 elements, then
// elementwise update. gamma/beta are per-channel scalars.
// ---------------------------------------------------------------------------
__global__ __launch_bounds__(256) void ode_kernel(
    const float* __restrict__ xt,        // [HW][BC]
    const float* __restrict__ delta_t,   // [NLAYERS]
    const float* __restrict__ matrices,  // [NLAYERS][256]
    const float* __restrict__ gamma,     // [HW]
    const float* __restrict__ beta,      // [HW]
    float* __restrict__ yt)              // [HW][BC]
{
    const int p = blockIdx.x;
    const int t = threadIdx.x;
    const int lane = t & 31;
    const int wid  = t >> 5;

    const float* __restrict__ xp = xt + (size_t)p * BC;

    float x1[16], y0[16], z[16];
#pragma unroll
    for (int u = 0; u < 16; ++u) {
        x1[u] = xp[u * 256 + t];
        y0[u] = x1[u];
    }

    const float gm = gamma[p];
    const float bt = beta[p];

    __shared__ float red_s[8];
    __shared__ float red_q[8];
    __shared__ float bc_ab[2];

    for (int l = 0; l < NLAYERS; ++l) {
        const float mt  = matrices[l * 256 + t];   // m_l[cij = t]
        float dtl = delta_t[l];
        dtl = fminf(fmaxf(dtl, 0.0f), 6.0f);       // relu6(delta_t)
        const float c1 = 1.0f - dtl;

        // pass 1: z = y0 + m*x1, accumulate sum & sumsq
        float s = 0.0f, q = 0.0f;
#pragma unroll
        for (int u = 0; u < 16; ++u) {
            const float zv = fmaf(mt, x1[u], y0[u]);
            z[u] = zv;
            s += zv;
            q = fmaf(zv, zv, q);
        }

        // warp reduce
#pragma unroll
        for (int off = 16; off > 0; off >>= 1) {
            s += __shfl_xor_sync(0xffffffffu, s, off);
            q += __shfl_xor_sync(0xffffffffu, q, off);
        }
        if (lane == 0) { red_s[wid] = s; red_q[wid] = q; }
        __syncthreads();
        if (t == 0) {
            float S = 0.0f, Q = 0.0f;
#pragma unroll
            for (int w = 0; w < 8; ++w) { S += red_s[w]; Q += red_q[w]; }
            const float inv  = 1.0f / 4096.0f;
            const float mean = S * inv;
            const float var  = fmaf(-mean, mean, Q * inv);   // E[z^2]-mu^2 (biased)
            const float rs   = rsqrtf(var + 1e-5f);
            const float a    = gm * rs;
            bc_ab[0] = a;
            bc_ab[1] = fmaf(-mean, a, bt);                    // beta - mean*a
        }
        __syncthreads();
        const float a  = bc_ab[0];
        const float bb = bc_ab[1];

        // pass 2: y0 = (1-dt)*y0 + dt*relu6(a*z + bb)
#pragma unroll
        for (int u = 0; u < 16; ++u) {
            float r = fmaf(z[u], a, bb);
            r = fminf(fmaxf(r, 0.0f), 6.0f);
            y0[u] = fmaf(dtl, r, c1 * y0[u]);
        }
    }

    float* __restrict__ yp = yt + (size_t)p * BC;
#pragma unroll
    for (int u = 0; u < 16; ++u)
        yp[u * 256 + t] = y0[u] + x1[u];
}

// ---------------------------------------------------------------------------
extern "C" void kernel_launch(void* const* d_in, const int* in_sizes, int n_in,
                              void* d_out, int out_size) {
    const float* x    = (const float*)d_in[0];   // [16,256,32,32]
    const float* dt   = (const float*)d_in[1];   // [30,1]
    const float* mat  = (const float*)d_in[2];   // [30,1,1,16,16]
    const float* gm   = (const float*)d_in[3];   // [1024]
    const float* bt   = (const float*)d_in[4];   // [1024]
    float* out = (float*)d_out;                  // [16,256,32,32]

    float *xt, *yt;
    cudaGetSymbolAddress((void**)&xt, g_xt);
    cudaGetSymbolAddress((void**)&yt, g_yt);

    dim3 blk(32, 8);
    // x: [BC=4096 rows, HW=1024 cols] -> xt: [1024, 4096]
    tr_kernel<BC, HW><<<dim3(HW / 32, BC / 32), blk>>>(x, xt);
    // fused 30-layer ODE, one CTA per channel
    ode_kernel<<<HW, 256>>>(xt, dt, mat, gm, bt, yt);
    // yt: [1024 rows, 4096 cols] -> out: [4096, 1024]
    tr_kernel<HW, BC><<<dim3(BC / 32, HW / 32), blk>>>(yt, out);
}

// round 3
// speedup vs baseline: 1.1467x; 1.1467x over previous
#include <cuda_runtime.h>

// x: [B=16, C=256, H=32, W=32] viewed [BC=4096][HW=1024].
// x1[b,p,cij] = x[b,cij,p]; 30 layers of per-channel(p) BN+relu6 ODE.
// Channels p independent -> one CTA per channel, state in registers.
// State kept as z̃ = z/alpha (alpha = prod c1) so the per-layer update is
// two packed FMAs; all bulk math uses f32x2 (FFMA2) to hit full fp32 rate.

constexpr int HW = 1024;
constexpr int BC = 4096;
constexpr int NL = 30;

__device__ float g_xt[(size_t)HW * BC];
__device__ float g_yt[(size_t)HW * BC];

typedef unsigned long long u64;

__device__ __forceinline__ u64 pk2(float x, float y) {
    u64 r; asm("mov.b64 %0,{%1,%2};" : "=l"(r) : "f"(x), "f"(y)); return r;
}
__device__ __forceinline__ void upk2(u64 v, float& x, float& y) {
    asm("mov.b64 {%0,%1},%2;" : "=f"(x), "=f"(y) : "l"(v));
}
__device__ __forceinline__ u64 fma2(u64 a, u64 b, u64 c) {
    u64 d; asm("fma.rn.f32x2 %0,%1,%2,%3;" : "=l"(d) : "l"(a), "l"(b), "l"(c)); return d;
}
__device__ __forceinline__ u64 add2(u64 a, u64 b) {
    u64 d; asm("add.rn.f32x2 %0,%1,%2;" : "=l"(d) : "l"(a), "l"(b)); return d;
}
__device__ __forceinline__ u64 mul2(u64 a, u64 b) {
    u64 d; asm("mul.rn.f32x2 %0,%1,%2;" : "=l"(d) : "l"(a), "l"(b)); return d;
}

// ---------------------------------------------------------------------------
// float4 tiled transpose, 64x64 tiles: out[c][r] = in[r][c]
// ---------------------------------------------------------------------------
template<int ROWS, int COLS>
__global__ __launch_bounds__(256) void tr4_kernel(const float* __restrict__ in,
                                                  float* __restrict__ out) {
    __shared__ float tile[64][65];
    const int bx = blockIdx.x * 64;           // column base (in)
    const int by = blockIdx.y * 64;           // row base (in)
    const int tx = threadIdx.x & 15;          // 16 float4 across
    const int ty = threadIdx.x >> 4;          // 16 rows per step
#pragma unroll
    for (int j = 0; j < 64; j += 16) {
        float4 v = *reinterpret_cast<const float4*>(
            in + (size_t)(by + ty + j) * COLS + bx + tx * 4);
        tile[ty + j][tx * 4 + 0] = v.x;
        tile[ty + j][tx * 4 + 1] = v.y;
        tile[ty + j][tx * 4 + 2] = v.z;
        tile[ty + j][tx * 4 + 3] = v.w;
    }
    __syncthreads();
#pragma unroll
    for (int j = 0; j < 64; j += 16) {
        const int r = ty + j;
        float4 v;
        v.x = tile[tx * 4 + 0][r];
        v.y = tile[tx * 4 + 1][r];
        v.z = tile[tx * 4 + 2][r];
        v.w = tile[tx * 4 + 3][r];
        *reinterpret_cast<float4*>(out + (size_t)(bx + r) * ROWS + by + tx * 4) = v;
    }
}

// ---------------------------------------------------------------------------
// Fused 30-layer ODE. One CTA per channel p, 256 threads, f32x2 math.
// Thread t owns (cij = t, b = 0..15) as 8 packed float2 (b pairs).
// Recursion on z̃: z̃' = z̃ + (dt*inva')*r + (k*inva')*x1, r = clamp(a'·z̃+bb).
// ---------------------------------------------------------------------------
__global__ __launch_bounds__(256, 4) void ode_kernel(
    const float* __restrict__ xt,        // [HW][BC]
    const float* __restrict__ dtg,       // [NL]
    const float* __restrict__ mats,      // [NL][256]
    const float* __restrict__ gamma,     // [HW]
    const float* __restrict__ beta,      // [HW]
    float* __restrict__ yt)              // [HW][BC]
{
    __shared__ float  sm_m[31 * 256];    // row 30 = 1.0 (folds final "+x1")
    __shared__ float  sm_dt[32];
    __shared__ float2 red[8];
    __shared__ float2 bcv;

    const int p = blockIdx.x;
    const int t = threadIdx.x;
    const int lane = t & 31;
    const int wid = t >> 5;

#pragma unroll
    for (int i = 0; i < 31; ++i)
        sm_m[i * 256 + t] = (i < NL) ? mats[i * 256 + t] : 1.0f;
    if (t < NL) {
        float d = dtg[t];
        sm_dt[t] = fminf(fmaxf(d, 0.0f), 6.0f);   // relu6(delta_t)
    }
    __syncthreads();

    const float gm = gamma[p];
    const float bt = beta[p];
    const float* __restrict__ xp = xt + (size_t)p * BC;

    u64 x1[8], z[8];
    {
        const float m0 = sm_m[t];
#pragma unroll
        for (int u = 0; u < 8; ++u) {
            const float a = xp[(2 * u) * 256 + t];
            const float b = xp[(2 * u + 1) * 256 + t];
            x1[u] = pk2(a, b);
            z[u]  = pk2(fmaf(m0, a, a), fmaf(m0, b, b));   // z1 = (1+m1)x1
        }
    }

    float inva = 1.0f;   // 1/alpha (alpha = prod c1), approx but self-consistent

    for (int l = 0; l < NL; ++l) {
        const float mt   = sm_m[l * 256 + t];
        const float mnx  = sm_m[(l + 1) * 256 + t];      // row 30 == 1.0
        const float dtl  = sm_dt[l];
        const float c1   = 1.0f - dtl;
        const float rc1  = __fdividef(1.0f, c1);
        const float ivn  = inva * rc1;                   // inva_{l+1}
        const float kk   = fmaf(-c1, mt, mnx);           // m_{l+1} - c1*m_l
        const float dts  = dtl * ivn;
        const float kps  = kk * ivn;
        const u64 dtp = pk2(dts, dts);
        const u64 kp  = pk2(kps, kps);

        // stats on z̃
        u64 s2 = 0ull, q2 = 0ull;
#pragma unroll
        for (int u = 0; u < 8; ++u) {
            s2 = add2(s2, z[u]);
            q2 = fma2(z[u], z[u], q2);
        }
        float sx, sy, qx, qy;
        upk2(s2, sx, sy); upk2(q2, qx, qy);
        float s = sx + sy, q = qx + qy;
#pragma unroll
        for (int o = 16; o > 0; o >>= 1) {
            s += __shfl_xor_sync(0xffffffffu, s, o);
            q += __shfl_xor_sync(0xffffffffu, q, o);
        }
        if (lane == 0) red[wid] = make_float2(s, q);
        __syncthreads();
        if (t == 0) {
            float S = 0.0f, Q = 0.0f;
#pragma unroll
            for (int w = 0; w < 8; ++w) { S += red[w].x; Q += red[w].y; }
            const float inv  = 1.0f / 4096.0f;
            const float mu   = S * inv;                      // mean of z̃
            const float va   = fmaf(-mu, mu, Q * inv);       // var of z̃
            const float epsn = 1e-5f * inva * inva;          // eps/alpha^2
            const float ap   = gm * rsqrtf(va + epsn);       // a * alpha
            bcv = make_float2(ap, fmaf(-mu, ap, bt));        // (a', bb)
        }
        __syncthreads();
        const float2 ab = bcv;
        const u64 a2 = pk2(ab.x, ab.x);
        const u64 b2 = pk2(ab.y, ab.y);

#pragma unroll
        for (int u = 0; u < 8; ++u) {
            u64 r2 = fma2(z[u], a2, b2);                     // a'*z̃ + bb (real scale)
            float rx, ry; upk2(r2, rx, ry);
            rx = fminf(fmaxf(rx, 0.0f), 6.0f);               // relu6 (FMNMX, alu pipe)
            ry = fminf(fmaxf(ry, 0.0f), 6.0f);
            r2 = pk2(rx, ry);
            z[u] = fma2(dtp, r2, z[u]);
            z[u] = fma2(kp, x1[u], z[u]);
        }
        inva = ivn;
    }

    // out = alpha * z̃_final  (final layer used k = 1 - c1*m so z̃ holds y+x1)
    const float alpha = __fdividef(1.0f, inva);
    const u64 al2 = pk2(alpha, alpha);
    float* __restrict__ yp = yt + (size_t)p * BC;
#pragma unroll
    for (int u = 0; u < 8; ++u) {
        u64 o2 = mul2(z[u], al2);
        float ox, oy; upk2(o2, ox, oy);
        yp[(2 * u) * 256 + t]     = ox;
        yp[(2 * u + 1) * 256 + t] = oy;
    }
}

// ---------------------------------------------------------------------------
extern "C" void kernel_launch(void* const* d_in, const int* in_sizes, int n_in,
                              void* d_out, int out_size) {
    const float* x   = (const float*)d_in[0];   // [16,256,32,32]
    const float* dt  = (const float*)d_in[1];   // [30,1]
    const float* mat = (const float*)d_in[2];   // [30,1,1,16,16]
    const float* gm  = (const float*)d_in[3];   // [1024]
    const float* bt  = (const float*)d_in[4];   // [1024]
    float* out = (float*)d_out;                 // [16,256,32,32]

    float *xt, *yt;
    cudaGetSymbolAddress((void**)&xt, g_xt);
    cudaGetSymbolAddress((void**)&yt, g_yt);

    // x: [4096 x 1024] -> xt: [1024 x 4096]
    tr4_kernel<BC, HW><<<dim3(HW / 64, BC / 64), 256>>>(x, xt);
    // fused 30-layer ODE, one CTA per channel
    ode_kernel<<<HW, 256>>>(xt, dt, mat, gm, bt, yt);
    // yt: [1024 x 4096] -> out: [4096 x 1024]
    tr4_kernel<HW, BC><<<dim3(BC / 64, HW / 64), 256>>>(yt, out);
}